// round 2
// baseline (speedup 1.0000x reference)
#include <cuda_runtime.h>
#include <math.h>

#define CIN 256
#define NCLS 91
#define NANC 9
#define TOPKN 1000
#define DETSN 300
#define CAP 16384
#define NEGV -1e9f
#define BBOX_CLIP 4.135166556742356f
#define IMGSZ 512.0f

// ---------------- scratch layout (float units) ----------------
#define OFF_WT_CT 0ull
#define OFF_WT_CL 2359296ull
#define OFF_WT_RT 4276224ull
#define OFF_WT_RB 6635520ull
#define OFF_BUFA  6782976ull
#define OFF_BUFB  7831552ull
#define OFF_LOG   8880128ull
#define OFF_REG   12288000ull
#define OFF_KEYS  12550144ull
#define OFF_CK    15904768ull
#define OFF_CI    15921152ull
#define OFF_SLS   15937536ull
#define OFF_SLI   15938536ull
#define OFF_CS    15939536ull
#define OFF_CB    15944536ull
#define OFF_CL2   15964536ull
#define TOTAL_F   15969536ull

__device__ __align__(16) float g_scratch[TOTAL_F];

struct SelState {
    int cnt, slotn, fillmode, b1, k2;
    unsigned T;
    int hist1[2048];
    int hist2[2048];
};
__device__ SelState d_st;
__device__ int g_gmax;

// ------------- weight transpose: w[Cout][256][3][3] -> wT[tap][ic][CoutPad] -------------
__global__ void transpose_w(const float* __restrict__ w, float* __restrict__ wT,
                            int Cout, int CoutPad) {
    int i = blockIdx.x * blockDim.x + threadIdx.x;
    int n = Cout * CIN * 9;
    if (i >= n) return;
    int oc = i / (CIN * 9);
    int r  = i % (CIN * 9);
    int ic = r / 9;
    int t  = r % 9;
    wT[(size_t)(t * CIN + ic) * CoutPad + oc] = w[i];
}

// ------------- 3x3 SAME conv, fp32, tap-decomposed implicit GEMM -------------
// grid: (ceil(HW/64), CoutPad/64), block 256 (16x16), each thread 4x4 micro-tile
__global__ void conv3x3_kernel(const float* __restrict__ in, const float* __restrict__ wT,
                               const float* __restrict__ bias, float* __restrict__ out,
                               int Cout, int CoutPad, int logW, int relu) {
    int W = 1 << logW;
    int H = W;
    int HW = H * W;
    int pxBase = blockIdx.x * 64;
    int ocBase = blockIdx.y * 64;
    __shared__ float As[16][64];
    __shared__ float Bs[16][64];
    int tid = threadIdx.x;
    int ty = tid >> 4, tx = tid & 15;
    float acc[4][4];
#pragma unroll
    for (int i = 0; i < 4; i++)
#pragma unroll
        for (int j = 0; j < 4; j++) acc[i][j] = 0.f;

    for (int tap = 0; tap < 9; ++tap) {
        int dy = tap / 3 - 1, dx = tap % 3 - 1;
        const float* wt = wT + (size_t)tap * CIN * CoutPad + ocBase;
        for (int kc = 0; kc < CIN; kc += 16) {
            __syncthreads();
#pragma unroll
            for (int i = 0; i < 4; ++i) {
                int e = tid + i * 256;
                int k = e >> 6, oc = e & 63;
                As[k][oc] = wt[(size_t)(kc + k) * CoutPad + oc];
            }
#pragma unroll
            for (int i = 0; i < 4; ++i) {
                int e = tid + i * 256;
                int k = e >> 6, px = e & 63;
                int p = pxBase + px;
                float v = 0.f;
                if (p < HW) {
                    int hh = (p >> logW) + dy;
                    int ww = (p & (W - 1)) + dx;
                    if ((unsigned)hh < (unsigned)H && (unsigned)ww < (unsigned)W)
                        v = in[(size_t)(kc + k) * HW + (hh << logW) + ww];
                }
                Bs[k][px] = v;
            }
            __syncthreads();
#pragma unroll
            for (int k = 0; k < 16; ++k) {
                float4 a = *(const float4*)&As[k][ty << 2];
                float4 b = *(const float4*)&Bs[k][tx << 2];
                float av[4] = {a.x, a.y, a.z, a.w};
                float bv[4] = {b.x, b.y, b.z, b.w};
#pragma unroll
                for (int i = 0; i < 4; i++)
#pragma unroll
                    for (int j = 0; j < 4; j++) acc[i][j] += av[i] * bv[j];
            }
        }
    }
#pragma unroll
    for (int i = 0; i < 4; i++) {
        int oc = ocBase + (ty << 2) + i;
        if (oc >= Cout) continue;
        float bvl = bias[oc];
#pragma unroll
        for (int j = 0; j < 4; j++) {
            int p = pxBase + (tx << 2) + j;
            if (p < HW) {
                float v = acc[i][j] + bvl;
                if (relu) v = fmaxf(v, 0.f);
                out[(size_t)oc * HW + p] = v;
            }
        }
    }
}

// ------------- sigmoid score keys (0 for score <= thresh) -------------
__global__ void keys_kernel(const float* __restrict__ logits, unsigned* __restrict__ keys,
                            int HW, int N) {
    int i = blockIdx.x * blockDim.x + threadIdx.x;
    if (i >= N) return;
    int c = i % NCLS;
    int r = i / NCLS;
    int a = r % NANC;
    int p = r / NANC;
    float lg = logits[(size_t)(a * NCLS + c) * HW + p];
    float s = 1.f / (1.f + expf(-lg));
    keys[i] = (s > 0.05f) ? __float_as_uint(s) : 0u;
}

__global__ void init_kernel() { g_gmax = 0; }

__global__ void zero_state_kernel() {
    int t = blockIdx.x * blockDim.x + threadIdx.x;
    if (t < 2048) { d_st.hist1[t] = 0; d_st.hist2[t] = 0; }
    if (t == 0) {
        d_st.cnt = 0; d_st.slotn = 0; d_st.fillmode = 0;
        d_st.b1 = -1; d_st.k2 = 0; d_st.T = 0u;
    }
}

__global__ void hist1_kernel(const unsigned* __restrict__ keys, int N) {
    __shared__ int h[2048];
    for (int i = threadIdx.x; i < 2048; i += blockDim.x) h[i] = 0;
    __syncthreads();
    for (int i = blockIdx.x * blockDim.x + threadIdx.x; i < N; i += gridDim.x * blockDim.x) {
        unsigned k = keys[i];
        if (k) atomicAdd(&h[k >> 21], 1);
    }
    __syncthreads();
    for (int i = threadIdx.x; i < 2048; i += blockDim.x)
        if (h[i]) atomicAdd(&d_st.hist1[i], h[i]);
}

__global__ void hist2_kernel(const unsigned* __restrict__ keys, int N) {
    __shared__ int h[2048];
    int b1 = d_st.b1;
    if (b1 < 0) return;
    for (int i = threadIdx.x; i < 2048; i += blockDim.x) h[i] = 0;
    __syncthreads();
    for (int i = blockIdx.x * blockDim.x + threadIdx.x; i < N; i += gridDim.x * blockDim.x) {
        unsigned k = keys[i];
        if (k && (int)(k >> 21) == b1) atomicAdd(&h[(k >> 10) & 2047], 1);
    }
    __syncthreads();
    for (int i = threadIdx.x; i < 2048; i += blockDim.x)
        if (h[i]) atomicAdd(&d_st.hist2[i], h[i]);
}

// single block 256 threads: suffix-sum + threshold select
__global__ void scan_kernel(int pass) {
    __shared__ int s0[2048], s1[2048];
    if (pass == 1 && d_st.fillmode) return;
    int* hist = (pass == 0) ? d_st.hist1 : d_st.hist2;
    int K = (pass == 0) ? TOPKN : d_st.k2;
    int t = threadIdx.x;
    for (int i = t; i < 2048; i += 256) s0[i] = hist[i];
    __syncthreads();
    int* src = s0; int* dst = s1;
    for (int d = 1; d < 2048; d <<= 1) {
        for (int i = t; i < 2048; i += 256)
            dst[i] = src[i] + ((i + d < 2048) ? src[i + d] : 0);
        __syncthreads();
        int* tmp = src; src = dst; dst = tmp;
    }
    if (pass == 0) {
        if (t == 0 && src[0] < K) { d_st.fillmode = 1; d_st.T = 1u; d_st.b1 = -1; }
        __syncthreads();
        if (src[0] >= K) {
            for (int i = t; i < 2048; i += 256) {
                if (src[i] >= K && (i == 2047 || src[i + 1] < K)) {
                    d_st.b1 = i;
                    d_st.k2 = K - ((i == 2047) ? 0 : src[i + 1]);
                }
            }
        }
    } else {
        int b1 = d_st.b1;
        for (int i = t; i < 2048; i += 256) {
            if (src[i] >= K && (i == 2047 || src[i + 1] < K))
                d_st.T = ((unsigned)((b1 << 11) | i)) << 10;
        }
    }
}

__global__ void compact_kernel(const unsigned* __restrict__ keys, int N,
                               unsigned* __restrict__ ck, int* __restrict__ ci) {
    unsigned T = d_st.T;
    for (int i = blockIdx.x * blockDim.x + threadIdx.x; i < N; i += gridDim.x * blockDim.x) {
        unsigned k = keys[i];
        if (k && k >= T) {
            int p = atomicAdd(&d_st.cnt, 1);
            if (p < CAP) { ck[p] = k; ci[p] = i; }
        }
    }
}

// single block 1024 threads, 128KB dyn smem, descending bitonic with tie = lowest index
__global__ void sort_kernel(const unsigned* __restrict__ ck, const int* __restrict__ ci,
                            float* __restrict__ slot_s, int* __restrict__ slot_i) {
    extern __shared__ unsigned long long s[];
    int M = d_st.cnt; if (M > CAP) M = CAP;
    for (int i = threadIdx.x; i < CAP; i += 1024)
        s[i] = (i < M) ? (((unsigned long long)ck[i] << 32) | (unsigned)(~(unsigned)ci[i])) : 0ull;
    __syncthreads();
    for (int k = 2; k <= CAP; k <<= 1) {
        for (int j = k >> 1; j > 0; j >>= 1) {
            for (int i = threadIdx.x; i < CAP; i += 1024) {
                int l = i ^ j;
                if (l > i) {
                    unsigned long long a = s[i], b = s[l];
                    bool up = ((i & k) == 0);   // descending overall
                    if (up ? (a < b) : (a > b)) { s[i] = b; s[l] = a; }
                }
            }
            __syncthreads();
        }
    }
    int outn = (M < TOPKN) ? M : TOPKN;
    for (int i = threadIdx.x; i < outn; i += 1024) {
        unsigned long long v = s[i];
        slot_s[i] = __uint_as_float((unsigned)(v >> 32));
        slot_i[i] = (int)(~(unsigned)(v & 0xffffffffull));
    }
    if (threadIdx.x == 0) d_st.slotn = outn;
}

// single block 1024 threads: fill remaining slots with first failing indices (ascending)
__global__ void fill_kernel(const unsigned* __restrict__ keys, int N,
                            float* __restrict__ slot_s, int* __restrict__ slot_i) {
    __shared__ int scn[1024];
    __shared__ int s_coll;
    int m = TOPKN - d_st.slotn;
    if (m <= 0) return;
    int base = d_st.slotn;
    if (threadIdx.x == 0) s_coll = 0;
    __syncthreads();
    for (int start = 0; start < N; start += 1024) {
        int collected = s_coll;
        if (collected >= m) break;
        int i = start + threadIdx.x;
        int fail = (i < N && keys[i] == 0u) ? 1 : 0;
        scn[threadIdx.x] = fail;
        __syncthreads();
        for (int d = 1; d < 1024; d <<= 1) {
            int v = scn[threadIdx.x];
            int add = (threadIdx.x >= (unsigned)d) ? scn[threadIdx.x - d] : 0;
            __syncthreads();
            scn[threadIdx.x] = v + add;
            __syncthreads();
        }
        int incl = scn[threadIdx.x];
        int excl = incl - fail;
        if (fail && collected + excl < m) {
            slot_s[base + collected + excl] = -1.0f;
            slot_i[base + collected + excl] = i;
        }
        __syncthreads();
        if (threadIdx.x == 1023) s_coll = collected + incl;
        __syncthreads();
    }
}

// ------------- decode + clip + global box-max -------------
__global__ void decode_kernel(const float* __restrict__ reg, const float* __restrict__ anchors,
                              const float* __restrict__ slot_s, const int* __restrict__ slot_i,
                              float* __restrict__ cand_s, float* __restrict__ cand_b,
                              int* __restrict__ cand_l, int HW, int aOff, int base) {
    int i = blockIdx.x * blockDim.x + threadIdx.x;
    if (i >= TOPKN) return;
    float sc = slot_s[i];
    int idx = slot_i[i];
    int c = idx % NCLS;
    int r = idx / NCLS;
    int a = r % NANC;
    int p = r / NANC;
    float r0 = reg[(size_t)(a * 4 + 0) * HW + p];
    float r1 = reg[(size_t)(a * 4 + 1) * HW + p];
    float r2 = reg[(size_t)(a * 4 + 2) * HW + p];
    float r3 = reg[(size_t)(a * 4 + 3) * HW + p];
    const float* an = anchors + (size_t)(aOff + r) * 4;
    float ax0 = an[0], ay0 = an[1], ax1 = an[2], ay1 = an[3];
    float w = ax1 - ax0, h = ay1 - ay0;
    float cx = ax0 + 0.5f * w, cy = ay0 + 0.5f * h;
    float dw = fminf(r2, BBOX_CLIP), dh = fminf(r3, BBOX_CLIP);
    float pcx = r0 * w + cx, pcy = r1 * h + cy;
    float pw = expf(dw) * w, ph = expf(dh) * h;
    float x0 = fminf(fmaxf(pcx - 0.5f * pw, 0.f), IMGSZ);
    float y0 = fminf(fmaxf(pcy - 0.5f * ph, 0.f), IMGSZ);
    float x1 = fminf(fmaxf(pcx + 0.5f * pw, 0.f), IMGSZ);
    float y1 = fminf(fmaxf(pcy + 0.5f * ph, 0.f), IMGSZ);
    int o = base + i;
    cand_s[o] = sc;
    cand_b[o * 4 + 0] = x0; cand_b[o * 4 + 1] = y0;
    cand_b[o * 4 + 2] = x1; cand_b[o * 4 + 3] = y1;
    cand_l[o] = c;
    float mx = fmaxf(fmaxf(x0, y0), fmaxf(x1, y1));
    atomicMax(&g_gmax, __float_as_int(mx));
}

// ------------- sequential NMS, single block 1024 threads, 5 entries/thread -------------
__global__ void nms_kernel(const float* __restrict__ cs, const float* __restrict__ cb,
                           const int* __restrict__ cl, float* __restrict__ out, int out_size) {
    __shared__ float rv[32];
    __shared__ int ri[32];
    __shared__ float sjv;
    __shared__ int sji;
    __shared__ float sb[5];
    __shared__ int sel[DETSN];
    __shared__ int val[DETSN];
    int t = threadIdx.x;
    float off1 = __int_as_float(g_gmax) + 1.0f;
    float alive[5], b0[5], b1v[5], b2[5], b3[5], ar[5];
#pragma unroll
    for (int k = 0; k < 5; k++) {
        int e = t + k * 1024;
        if (e < 5000) {
            float s = cs[e];
            float o = (float)cl[e] * off1;
            float x0 = cb[e * 4 + 0] + o, y0 = cb[e * 4 + 1] + o;
            float x1 = cb[e * 4 + 2] + o, y1 = cb[e * 4 + 3] + o;
            b0[k] = x0; b1v[k] = y0; b2[k] = x1; b3[k] = y1;
            ar[k] = (x1 - x0) * (y1 - y0);
            alive[k] = (s > 0.05f) ? s : NEGV;
        } else {
            alive[k] = -3.0e38f;
            b0[k] = b1v[k] = b2[k] = b3[k] = 0.f; ar[k] = 0.f;
        }
    }
    for (int it = 0; it < DETSN; ++it) {
        float bv = -3.4e38f; int bi = 0x7fffffff;
#pragma unroll
        for (int k = 0; k < 5; k++) {
            int e = t + k * 1024;
            float v = alive[k];
            if (v > bv || (v == bv && e < bi)) { bv = v; bi = e; }
        }
        for (int o = 16; o > 0; o >>= 1) {
            float ov = __shfl_down_sync(0xffffffffu, bv, o);
            int oi = __shfl_down_sync(0xffffffffu, bi, o);
            if (ov > bv || (ov == bv && oi < bi)) { bv = ov; bi = oi; }
        }
        if ((t & 31) == 0) { rv[t >> 5] = bv; ri[t >> 5] = bi; }
        __syncthreads();
        if (t < 32) {
            bv = rv[t]; bi = ri[t];
            for (int o = 16; o > 0; o >>= 1) {
                float ov = __shfl_down_sync(0xffffffffu, bv, o);
                int oi = __shfl_down_sync(0xffffffffu, bi, o);
                if (ov > bv || (ov == bv && oi < bi)) { bv = ov; bi = oi; }
            }
            if (t == 0) { sjv = bv; sji = bi; }
        }
        __syncthreads();
        int j = sji; float vj = sjv;
        if (t == (j & 1023)) {
            int k = j >> 10;
            sb[0] = b0[k]; sb[1] = b1v[k]; sb[2] = b2[k]; sb[3] = b3[k]; sb[4] = ar[k];
            alive[k] = NEGV;
        }
        if (t == 0) { sel[it] = j; val[it] = (vj > 0.05f) ? 1 : 0; }
        __syncthreads();
        float jx0 = sb[0], jy0 = sb[1], jx1 = sb[2], jy1 = sb[3], ja = sb[4];
#pragma unroll
        for (int k = 0; k < 5; k++) {
            float lt0 = fmaxf(jx0, b0[k]), lt1 = fmaxf(jy0, b1v[k]);
            float rb0 = fminf(jx1, b2[k]), rb1 = fminf(jy1, b3[k]);
            float w = fmaxf(rb0 - lt0, 0.f), h = fmaxf(rb1 - lt1, 0.f);
            float inter = w * h;
            float iou = inter / (ja + ar[k] - inter + 1e-12f);
            if (iou > 0.5f) alive[k] = NEGV;
        }
        __syncthreads();
    }
    // write outputs: 300 rows of (s, x0, y0, x1, y1), then 300 labels as float
    for (int i = t; i < DETSN; i += 1024) {
        int j = sel[i]; int v = val[i];
        if (i * 5 + 4 < out_size) {
            out[i * 5 + 0] = v ? cs[j] : 0.f;
            out[i * 5 + 1] = v ? cb[j * 4 + 0] : 0.f;
            out[i * 5 + 2] = v ? cb[j * 4 + 1] : 0.f;
            out[i * 5 + 3] = v ? cb[j * 4 + 2] : 0.f;
            out[i * 5 + 4] = v ? cb[j * 4 + 3] : 0.f;
        }
        int li = DETSN * 5 + i;
        if (li < out_size) out[li] = v ? (float)cl[j] : -1.0f;
    }
    for (int i = DETSN * 6 + t; i < out_size; i += 1024) out[i] = 0.f;
}

extern "C" void kernel_launch(void* const* d_in, const int* in_sizes, int n_in,
                              void* d_out, int out_size) {
    const float* feat[5];
    for (int i = 0; i < 5; i++) feat[i] = (const float*)d_in[i];
    const float* anchors = (const float*)d_in[5];
    const float* ctw = (const float*)d_in[6];
    const float* ctb = (const float*)d_in[7];
    const float* cow = (const float*)d_in[8];
    const float* cob = (const float*)d_in[9];
    const float* rtw = (const float*)d_in[10];
    const float* rtb = (const float*)d_in[11];
    const float* rbw = (const float*)d_in[12];
    const float* rbb = (const float*)d_in[13];

    float* S = nullptr;
    cudaGetSymbolAddress((void**)&S, g_scratch);
    cudaFuncSetAttribute(sort_kernel, cudaFuncAttributeMaxDynamicSharedMemorySize, CAP * 8);

    // weight transposes
    const int TW = 256 * 256 * 9;  // 589824
    for (int i = 0; i < 4; i++) {
        transpose_w<<<(TW + 255) / 256, 256>>>(ctw + (size_t)i * TW, S + OFF_WT_CT + (size_t)i * TW, 256, 256);
        transpose_w<<<(TW + 255) / 256, 256>>>(rtw + (size_t)i * TW, S + OFF_WT_RT + (size_t)i * TW, 256, 256);
    }
    {
        int n = (NANC * NCLS) * CIN * 9;
        transpose_w<<<(n + 255) / 256, 256>>>(cow, S + OFF_WT_CL, NANC * NCLS, 832);
        int n2 = (NANC * 4) * CIN * 9;
        transpose_w<<<(n2 + 255) / 256, 256>>>(rbw, S + OFF_WT_RB, NANC * 4, 64);
    }
    init_kernel<<<1, 1>>>();

    const int HWs[5]  = {4096, 1024, 256, 64, 16};
    const int logWs[5] = {6, 5, 4, 3, 2};
    int aOff = 0;

    unsigned* keys = (unsigned*)(S + OFF_KEYS);
    unsigned* ck = (unsigned*)(S + OFF_CK);
    int* ci = (int*)(S + OFF_CI);
    float* sls = S + OFF_SLS;
    int* sli = (int*)(S + OFF_SLI);
    float* cand_s = S + OFF_CS;
    float* cand_b = S + OFF_CB;
    int* cand_l = (int*)(S + OFF_CL2);

    for (int l = 0; l < 5; l++) {
        int HW = HWs[l], lw = logWs[l];
        int gx = (HW + 63) / 64;
        dim3 gt(gx, 4), gl(gx, 13), gr(gx, 1);

        // cls tower + logits
        conv3x3_kernel<<<gt, 256>>>(feat[l], S + OFF_WT_CT + 0 * (size_t)TW, ctb + 0 * 256, S + OFF_BUFA, 256, 256, lw, 1);
        conv3x3_kernel<<<gt, 256>>>(S + OFF_BUFA, S + OFF_WT_CT + 1 * (size_t)TW, ctb + 1 * 256, S + OFF_BUFB, 256, 256, lw, 1);
        conv3x3_kernel<<<gt, 256>>>(S + OFF_BUFB, S + OFF_WT_CT + 2 * (size_t)TW, ctb + 2 * 256, S + OFF_BUFA, 256, 256, lw, 1);
        conv3x3_kernel<<<gt, 256>>>(S + OFF_BUFA, S + OFF_WT_CT + 3 * (size_t)TW, ctb + 3 * 256, S + OFF_BUFB, 256, 256, lw, 1);
        conv3x3_kernel<<<gl, 256>>>(S + OFF_BUFB, S + OFF_WT_CL, cob, S + OFF_LOG, NANC * NCLS, 832, lw, 0);

        // reg tower + bbox
        conv3x3_kernel<<<gt, 256>>>(feat[l], S + OFF_WT_RT + 0 * (size_t)TW, rtb + 0 * 256, S + OFF_BUFA, 256, 256, lw, 1);
        conv3x3_kernel<<<gt, 256>>>(S + OFF_BUFA, S + OFF_WT_RT + 1 * (size_t)TW, rtb + 1 * 256, S + OFF_BUFB, 256, 256, lw, 1);
        conv3x3_kernel<<<gt, 256>>>(S + OFF_BUFB, S + OFF_WT_RT + 2 * (size_t)TW, rtb + 2 * 256, S + OFF_BUFA, 256, 256, lw, 1);
        conv3x3_kernel<<<gt, 256>>>(S + OFF_BUFA, S + OFF_WT_RT + 3 * (size_t)TW, rtb + 3 * 256, S + OFF_BUFB, 256, 256, lw, 1);
        conv3x3_kernel<<<gr, 256>>>(S + OFF_BUFB, S + OFF_WT_RB, rbb, S + OFF_REG, NANC * 4, 64, lw, 0);

        // per-level exact top-1000
        int N = HW * NANC * NCLS;
        keys_kernel<<<(N + 255) / 256, 256>>>(S + OFF_LOG, keys, HW, N);
        zero_state_kernel<<<8, 256>>>();
        hist1_kernel<<<256, 256>>>(keys, N);
        scan_kernel<<<1, 256>>>(0);
        hist2_kernel<<<256, 256>>>(keys, N);
        scan_kernel<<<1, 256>>>(1);
        compact_kernel<<<256, 256>>>(keys, N, ck, ci);
        sort_kernel<<<1, 1024, CAP * 8>>>(ck, ci, sls, sli);
        fill_kernel<<<1, 1024>>>(keys, N, sls, sli);
        decode_kernel<<<4, 256>>>(S + OFF_REG, anchors, sls, sli, cand_s, cand_b, cand_l, HW, aOff, l * TOPKN);
        aOff += HW * NANC;
    }

    nms_kernel<<<1, 1024>>>(cand_s, cand_b, cand_l, (float*)d_out, out_size);
}